// round 14
// baseline (speedup 1.0000x reference)
#include <cuda_runtime.h>
#include <cuda_fp16.h>
#include <math.h>

#define DISP 3
#define CH   256
#define HH   56
#define WW   56
#define WS2  49
#define XRP  40    // xr pitch (halves) — 80B row stride, LDSM conflict-free
#define SSP  40    // ss pitch (halves), row-major
#define MTP  40    // MT/PT pitch (halves)
#define BTP  56    // btab row pitch (floats): cols 49..55 = -1e30 padding
#define TSTR 2752  // per-type btab stride (floats), 49*56=2744 padded

__device__ __half g_MT[1024];  // MT[n][k] = (Wq^T Wk / sqrt32 * log2e)[k][n]
__device__ __half g_PT[1024];  // PT[n][k] = (Wv^T Wl^T)[k][n]
__device__ __align__(16) float g_btab[4 * TSTR];  // bias-2 (log2e) or -1e30; L1/L2-hot
__device__ int g_srow[64 * 64];                   // gather row*56+col per (win, token)

__device__ __forceinline__ unsigned pack_h2(float lo, float hi) {
    unsigned u;
    asm("cvt.rn.f16x2.f32 %0, %1, %2;" : "=r"(u) : "f"(hi), "f"(lo));
    return u;
}
__device__ __forceinline__ float ex2f(float x) {
    float r; asm("ex2.approx.f32 %0, %1;" : "=f"(r) : "f"(x));
    return r;
}

__device__ __forceinline__ void mma_f16(float& c0, float& c1, float& c2, float& c3,
                                        unsigned a0, unsigned a1, unsigned a2, unsigned a3,
                                        unsigned b0, unsigned b1) {
    asm volatile("mma.sync.aligned.m16n8k16.row.col.f32.f16.f16.f32 "
        "{%0,%1,%2,%3}, {%4,%5,%6,%7}, {%8,%9}, {%0,%1,%2,%3};"
        : "+f"(c0), "+f"(c1), "+f"(c2), "+f"(c3)
        : "r"(a0), "r"(a1), "r"(a2), "r"(a3), "r"(b0), "r"(b1));
}

__device__ __forceinline__ void ldsm_x4(unsigned addr, unsigned& r0, unsigned& r1,
                                        unsigned& r2, unsigned& r3) {
    asm volatile("ldmatrix.sync.aligned.m8n8.x4.shared.b16 {%0,%1,%2,%3}, [%4];"
        : "=r"(r0), "=r"(r1), "=r"(r2), "=r"(r3) : "r"(addr));
}
__device__ __forceinline__ void ldsm_x4_t(unsigned addr, unsigned& r0, unsigned& r1,
                                          unsigned& r2, unsigned& r3) {
    asm volatile("ldmatrix.sync.aligned.m8n8.x4.trans.shared.b16 {%0,%1,%2,%3}, [%4];"
        : "=r"(r0), "=r"(r1), "=r"(r2), "=r"(r3) : "r"(addr));
}

#define LOG2E 1.4426950408889634f

__global__ void precompute_kernel(const float* __restrict__ Wq,
                                  const float* __restrict__ Wk,
                                  const float* __restrict__ Wv,
                                  const float* __restrict__ Wl,
                                  const float* __restrict__ pe) {
    int i = blockIdx.x * 128 + threadIdx.x;   // 0..8191
    if (i < 1024) {   // fused weights
        int c = i >> 5, d = i & 31;
        float m = 0.f, p = 0.f;
#pragma unroll
        for (int j = 0; j < 32; ++j) {
            m += Wq[j * 32 + c] * Wk[j * 32 + d];   // (Wq^T Wk)[c][d]
            p += Wv[j * 32 + c] * Wl[d * 32 + j];   // (Wv^T Wl^T)[c][d]
        }
        g_MT[d * 32 + c] = __float2half_rn(m * 0.17677669529663687f * LOG2E);
        g_PT[d * 32 + c] = __float2half_rn(p);
    }
    // bias+mask tables: 4 types x 49 rows x BTP cols; masked/pad = -1e30
    for (int e = i; e < 4 * TSTR; e += 8192) {
        int type = e / TSTR, rem = e - type * TSTR;
        float v = -1e30f;
        if (rem < 49 * BTP) {
            int r = rem / BTP, cl = rem - r * BTP;
            if (cl < 49) {
                int qi = r / 7, qj = r - qi * 7;
                int ki = cl / 7, kj = cl - ki * 7;
                bool mrow = type & 1, mcol = type & 2;
                bool dead = (mrow && ((qi >= 4) != (ki >= 4))) ||
                            (mcol && ((qj >= 4) != (kj >= 4)));
                v = dead ? -1e30f : pe[(ki - qi + 6) * 13 + (kj - qj + 6)] * LOG2E - 2.0f;
            }
        }
        g_btab[e] = v;
    }
    // gather index table: 64 windows x 64 tokens
    if (i < 4096) {
        int w = i >> 6, t = i & 63;
        int sr = 0;
        if (t < WS2) {
            int nh = w >> 3, nw = w & 7;
            int wi = t / 7, wj = t - wi * 7;
            int rr = nh * 7 + wi + DISP;  if (rr >= HH) rr -= HH;
            int cc = nw * 7 + wj + DISP;  if (cc >= WW) cc -= WW;
            sr = rr * WW + cc;
        }
        g_srow[i] = sr;
    }
}

__global__ __launch_bounds__(128, 10)
void swca_kernel(const float* __restrict__ x, const float* __restrict__ skip,
                 float* __restrict__ out) {
    const int win   = blockIdx.x;   // 0..63
    const int head  = blockIdx.y;
    const int batch = blockIdx.z;
    const int nh = win >> 3, nw = win & 7;
    const int tid  = threadIdx.x;
    const int lane = tid & 31, warp = tid >> 5;
    const int lr = lane >> 2, lc = lane & 3;
    const int m0 = warp * 16;

    __shared__ __align__(16) __half xr[64 * XRP];   // x tile row-major [token][d]
    __shared__ __align__(16) __half ss[64 * SSP];   // skip tile row-major [token][d]
    __shared__ __align__(16) __half Ms[32 * MTP];
    __shared__ __align__(16) __half Ps[32 * MTP];

    const int* srow = g_srow + (win << 6);   // L2-hot (shared by 128 CTAs)
    const int r0 = m0 + lr, r1 = r0 + 8;

    // ==== scores accumulator = bias table (issued FIRST; latency hidden) ====
    float sc[7][4];
    {
        const int type = ((nh == 7) ? 1 : 0) | ((nw == 7) ? 2 : 0);
        int rq0 = r0 < 49 ? r0 : 48, rq1 = r1 < 49 ? r1 : 48;
        const float* bt0 = g_btab + type * TSTR + rq0 * BTP + 2 * lc;
        const float* bt1 = g_btab + type * TSTR + rq1 * BTP + 2 * lc;
#pragma unroll
        for (int nt = 0; nt < 7; ++nt) {
            *(float2*)&sc[nt][0] = __ldg((const float2*)(bt0 + nt * 8));
            *(float2*)&sc[nt][2] = __ldg((const float2*)(bt1 + nt * 8));
        }
    }
    // epilogue scatter rows (issued early, L2-hot)
    const int sr0 = __ldg(srow + (r0 < WS2 ? r0 : 0));
    const int sr1 = __ldg(srow + (r1 < WS2 ? r1 : 0));

    {   // copy weights: 1 LDG.128 + 1 STS.128 each
        int r = tid >> 2, ch = (tid & 3) << 3;
        *(uint4*)&Ms[r * MTP + ch] = *(const uint4*)&g_MT[r * 32 + ch];
        *(uint4*)&Ps[r * MTP + ch] = *(const uint4*)&g_PT[r * 32 + ch];
    }

    const size_t base = (size_t)batch * (HH * WW) * CH + head * 32;

    // ---- gather: both tiles row-major half (rows >= 49 zeroed); srow via table
    for (int idx = tid; idx < 512; idx += 128) {
        int t = idx >> 3, c4 = (idx & 7) << 2;
        float4 xv = make_float4(0.f, 0.f, 0.f, 0.f);
        float4 sv = xv;
        if (t < WS2) {
            size_t g = base + (size_t)__ldg(srow + t) * CH + c4;
            xv = *(const float4*)(x + g);
            sv = *(const float4*)(skip + g);
        }
        *(uint2*)&xr[t * XRP + c4] = make_uint2(pack_h2(xv.x, xv.y), pack_h2(xv.z, xv.w));
        *(uint2*)&ss[t * SSP + c4] = make_uint2(pack_h2(sv.x, sv.y), pack_h2(sv.z, sv.w));
    }
    __syncthreads();   // the only block-wide barrier

    // ---- LDSM lane-address bases
    const int l7 = lane & 7, lh = lane >> 3;
    const unsigned xrB = (unsigned)__cvta_generic_to_shared(xr) + 2u * (l7 * XRP + lh * 8);
    const unsigned msB = (unsigned)__cvta_generic_to_shared(Ms) + 2u * (l7 * MTP + lh * 8);
    const unsigned psB = (unsigned)__cvta_generic_to_shared(Ps) + 2u * (l7 * MTP + lh * 8);
    const unsigned xrA = (unsigned)__cvta_generic_to_shared(xr)
                       + 2u * ((m0 + ((lh & 1) << 3) + l7) * XRP + ((lh >> 1) << 3));
    const unsigned ssT = (unsigned)__cvta_generic_to_shared(ss) + 2u * ((lh * 8 + l7) * SSP);

    // ======== qm = x @ M (log2e pre-folded into M) ========
    unsigned qa[2][4];
    {
        unsigned xa[2][4];
        ldsm_x4(xrA,           xa[0][0], xa[0][1], xa[0][2], xa[0][3]);
        ldsm_x4(xrA + 2u * 16, xa[1][0], xa[1][1], xa[1][2], xa[1][3]);
#pragma unroll
        for (int np = 0; np < 2; ++np) {
            float qc[2][4];
#pragma unroll
            for (int k = 0; k < 2; ++k) {
                int nt = np * 2 + k;
                unsigned b0, b1, b2, b3;
                ldsm_x4(msB + 2u * (nt * 8 * MTP), b0, b1, b2, b3);
                float c0 = 0.f, c1 = 0.f, c2 = 0.f, c3 = 0.f;
                mma_f16(c0, c1, c2, c3, xa[0][0], xa[0][1], xa[0][2], xa[0][3], b0, b1);
                mma_f16(c0, c1, c2, c3, xa[1][0], xa[1][1], xa[1][2], xa[1][3], b2, b3);
                qc[k][0] = c0; qc[k][1] = c1; qc[k][2] = c2; qc[k][3] = c3;
            }
            qa[np][0] = pack_h2(qc[0][0], qc[0][1]);
            qa[np][1] = pack_h2(qc[0][2], qc[0][3]);
            qa[np][2] = pack_h2(qc[1][0], qc[1][1]);
            qa[np][3] = pack_h2(qc[1][2], qc[1][3]);
        }
    }

    // ======== scores = bias + qm @ x^T (bias already in accumulators) ========
#pragma unroll
    for (int nt = 0; nt < 7; ++nt) {
        unsigned b0, b1, b2, b3;
        ldsm_x4(xrB + 2u * (nt * 8 * XRP), b0, b1, b2, b3);
        mma_f16(sc[nt][0], sc[nt][1], sc[nt][2], sc[nt][3],
                qa[0][0], qa[0][1], qa[0][2], qa[0][3], b0, b1);
        mma_f16(sc[nt][0], sc[nt][1], sc[nt][2], sc[nt][3],
                qa[1][0], qa[1][1], qa[1][2], qa[1][3], b2, b3);
    }

    // ======== softmax: direct exp2, deferred normalization, NO max pass;
    //          pack probs into aa IN-PLACE so sc dies here (register diet) ====
    unsigned aa[4][4];
    float inv0, inv1;
    {
        float sm0 = 0.f, sm1 = 0.f;
#pragma unroll
        for (int nt = 0; nt < 7; ++nt) {
            float p0 = ex2f(sc[nt][0]);
            float p1 = ex2f(sc[nt][1]);
            float p2 = ex2f(sc[nt][2]);
            float p3 = ex2f(sc[nt][3]);
            sm0 += p0 + p1; sm1 += p2 + p3;
            // pack immediately: aa[kk][reg] layout (kk = nt>>1)
            if ((nt & 1) == 0) {
                aa[nt >> 1][0] = pack_h2(p0, p1);
                aa[nt >> 1][1] = pack_h2(p2, p3);
            } else {
                aa[nt >> 1][2] = pack_h2(p0, p1);
                aa[nt >> 1][3] = pack_h2(p2, p3);
            }
        }
        aa[3][2] = 0u;
        aa[3][3] = 0u;
        sm0 += __shfl_xor_sync(0xffffffffu, sm0, 1);
        sm0 += __shfl_xor_sync(0xffffffffu, sm0, 2);
        sm1 += __shfl_xor_sync(0xffffffffu, sm1, 1);
        sm1 += __shfl_xor_sync(0xffffffffu, sm1, 2);
        inv0 = __fdividef(1.f, sm0);
        inv1 = __fdividef(1.f, sm1);
    }

    // ======== T = probs @ skip_v (B via ldmatrix.trans) ========
    unsigned ta[2][4];
    {
        float tc[4][4];
#pragma unroll
        for (int nt = 0; nt < 4; ++nt) {
            float c0 = 0.f, c1 = 0.f, c2 = 0.f, c3 = 0.f;
#pragma unroll
            for (int tg = 0; tg < 2; ++tg) {
                unsigned b0, b1, b2, b3;
                ldsm_x4_t(ssT + 2u * (tg * 32 * SSP + nt * 8), b0, b1, b2, b3);
                mma_f16(c0, c1, c2, c3,
                        aa[2 * tg][0], aa[2 * tg][1], aa[2 * tg][2], aa[2 * tg][3], b0, b1);
                mma_f16(c0, c1, c2, c3,
                        aa[2 * tg + 1][0], aa[2 * tg + 1][1], aa[2 * tg + 1][2], aa[2 * tg + 1][3], b2, b3);
            }
            tc[nt][0] = c0; tc[nt][1] = c1; tc[nt][2] = c2; tc[nt][3] = c3;
        }
#pragma unroll
        for (int kk = 0; kk < 2; ++kk) {
            ta[kk][0] = pack_h2(tc[2 * kk][0],     tc[2 * kk][1]);
            ta[kk][1] = pack_h2(tc[2 * kk][2],     tc[2 * kk][3]);
            ta[kk][2] = pack_h2(tc[2 * kk + 1][0], tc[2 * kk + 1][1]);
            ta[kk][3] = pack_h2(tc[2 * kk + 1][2], tc[2 * kk + 1][3]);
        }
    }

    // ======== out = T @ P, scale rows by 1/sum, write ========
    {
        bool w0 = r0 < WS2, w1 = r1 < WS2;
        size_t g0 = base + (size_t)sr0 * CH;
        size_t g1 = base + (size_t)sr1 * CH;
#pragma unroll
        for (int nt = 0; nt < 4; ++nt) {
            unsigned b0, b1, b2, b3;
            ldsm_x4(psB + 2u * (nt * 8 * MTP), b0, b1, b2, b3);
            float c0 = 0.f, c1 = 0.f, c2 = 0.f, c3 = 0.f;
            mma_f16(c0, c1, c2, c3, ta[0][0], ta[0][1], ta[0][2], ta[0][3], b0, b1);
            mma_f16(c0, c1, c2, c3, ta[1][0], ta[1][1], ta[1][2], ta[1][3], b2, b3);
            int col = nt * 8 + 2 * lc;
            if (w0) *(float2*)(out + g0 + col) = make_float2(c0 * inv0, c1 * inv0);
            if (w1) *(float2*)(out + g1 + col) = make_float2(c2 * inv1, c3 * inv1);
        }
    }
}

extern "C" void kernel_launch(void* const* d_in, const int* in_sizes, int n_in,
                              void* d_out, int out_size) {
    const float* skip = (const float*)d_in[0];
    const float* x    = (const float*)d_in[1];
    const float* Wq   = (const float*)d_in[2];
    const float* Wk   = (const float*)d_in[3];
    const float* Wv   = (const float*)d_in[4];
    const float* Wl   = (const float*)d_in[5];
    const float* pe   = (const float*)d_in[6];
    (void)in_sizes; (void)n_in; (void)out_size;

    precompute_kernel<<<64, 128>>>(Wq, Wk, Wv, Wl, pe);
    dim3 grid(64, 8, 16);
    swca_kernel<<<grid, 128>>>(x, skip, (float*)d_out);
}

// round 15
// speedup vs baseline: 1.0852x; 1.0852x over previous
#include <cuda_runtime.h>
#include <cuda_fp16.h>
#include <math.h>

#define DISP 3
#define CH   256
#define HH   56
#define WW   56
#define WS2  49
#define XRP  40    // xr pitch (halves) — 80B row stride, LDSM conflict-free
#define SSP  40    // ss pitch (halves), row-major
#define MTP  40    // MT/PT pitch (halves)
#define BTP  56    // btab row pitch (floats): cols 49..55 = -1e30 padding
#define TSTR 2752  // per-type btab stride (floats), 49*56=2744 padded

__device__ __half g_MT[1024];  // MT[n][k] = (Wq^T Wk / sqrt32 * log2e)[k][n]
__device__ __half g_PT[1024];  // PT[n][k] = (Wv^T Wl^T)[k][n]
__device__ __align__(16) float g_btab[4 * TSTR];  // bias-2 (log2e) or -1e30; L1/L2-hot
__device__ int g_srow[64 * 64];                   // gather row*56+col per (win, token)

__device__ __forceinline__ unsigned pack_h2(float lo, float hi) {
    unsigned u;
    asm("cvt.rn.f16x2.f32 %0, %1, %2;" : "=r"(u) : "f"(hi), "f"(lo));
    return u;
}
__device__ __forceinline__ float ex2f(float x) {
    float r; asm("ex2.approx.f32 %0, %1;" : "=f"(r) : "f"(x));
    return r;
}

__device__ __forceinline__ void mma_f16(float& c0, float& c1, float& c2, float& c3,
                                        unsigned a0, unsigned a1, unsigned a2, unsigned a3,
                                        unsigned b0, unsigned b1) {
    asm volatile("mma.sync.aligned.m16n8k16.row.col.f32.f16.f16.f32 "
        "{%0,%1,%2,%3}, {%4,%5,%6,%7}, {%8,%9}, {%0,%1,%2,%3};"
        : "+f"(c0), "+f"(c1), "+f"(c2), "+f"(c3)
        : "r"(a0), "r"(a1), "r"(a2), "r"(a3), "r"(b0), "r"(b1));
}

__device__ __forceinline__ void ldsm_x4(unsigned addr, unsigned& r0, unsigned& r1,
                                        unsigned& r2, unsigned& r3) {
    asm volatile("ldmatrix.sync.aligned.m8n8.x4.shared.b16 {%0,%1,%2,%3}, [%4];"
        : "=r"(r0), "=r"(r1), "=r"(r2), "=r"(r3) : "r"(addr));
}
__device__ __forceinline__ void ldsm_x4_t(unsigned addr, unsigned& r0, unsigned& r1,
                                          unsigned& r2, unsigned& r3) {
    asm volatile("ldmatrix.sync.aligned.m8n8.x4.trans.shared.b16 {%0,%1,%2,%3}, [%4];"
        : "=r"(r0), "=r"(r1), "=r"(r2), "=r"(r3) : "r"(addr));
}

#define LOG2E 1.4426950408889634f

__global__ void precompute_kernel(const float* __restrict__ Wq,
                                  const float* __restrict__ Wk,
                                  const float* __restrict__ Wv,
                                  const float* __restrict__ Wl,
                                  const float* __restrict__ pe) {
    int i = blockIdx.x * 128 + threadIdx.x;   // 0..8191
    if (i < 1024) {   // fused weights
        int c = i >> 5, d = i & 31;
        float m = 0.f, p = 0.f;
#pragma unroll
        for (int j = 0; j < 32; ++j) {
            m += Wq[j * 32 + c] * Wk[j * 32 + d];   // (Wq^T Wk)[c][d]
            p += Wv[j * 32 + c] * Wl[d * 32 + j];   // (Wv^T Wl^T)[c][d]
        }
        g_MT[d * 32 + c] = __float2half_rn(m * 0.17677669529663687f * LOG2E);
        g_PT[d * 32 + c] = __float2half_rn(p);
    }
    // bias+mask tables: 4 types x 49 rows x BTP cols; masked/pad = -1e30
    for (int e = i; e < 4 * TSTR; e += 8192) {
        int type = e / TSTR, rem = e - type * TSTR;
        float v = -1e30f;
        if (rem < 49 * BTP) {
            int r = rem / BTP, cl = rem - r * BTP;
            if (cl < 49) {
                int qi = r / 7, qj = r - qi * 7;
                int ki = cl / 7, kj = cl - ki * 7;
                bool mrow = type & 1, mcol = type & 2;
                bool dead = (mrow && ((qi >= 4) != (ki >= 4))) ||
                            (mcol && ((qj >= 4) != (kj >= 4)));
                v = dead ? -1e30f : pe[(ki - qi + 6) * 13 + (kj - qj + 6)] * LOG2E - 2.0f;
            }
        }
        g_btab[e] = v;
    }
    // gather index table: 64 windows x 64 tokens
    if (i < 4096) {
        int w = i >> 6, t = i & 63;
        int sr = 0;
        if (t < WS2) {
            int nh = w >> 3, nw = w & 7;
            int wi = t / 7, wj = t - wi * 7;
            int rr = nh * 7 + wi + DISP;  if (rr >= HH) rr -= HH;
            int cc = nw * 7 + wj + DISP;  if (cc >= WW) cc -= WW;
            sr = rr * WW + cc;
        }
        g_srow[i] = sr;
    }
}

__global__ __launch_bounds__(128, 8)
void swca_kernel(const float* __restrict__ x, const float* __restrict__ skip,
                 float* __restrict__ out) {
    const int win   = blockIdx.x;   // 0..63
    const int head  = blockIdx.y;
    const int batch = blockIdx.z;
    const int nh = win >> 3, nw = win & 7;
    const int tid  = threadIdx.x;
    const int lane = tid & 31, warp = tid >> 5;
    const int lr = lane >> 2, lc = lane & 3;
    const int m0 = warp * 16;

    __shared__ __align__(16) __half xr[64 * XRP];   // x tile row-major [token][d]
    __shared__ __align__(16) __half ss[64 * SSP];   // skip tile row-major [token][d]
    __shared__ __align__(16) __half Ms[32 * MTP];
    __shared__ __align__(16) __half Ps[32 * MTP];

    const int* srow = g_srow + (win << 6);   // L2-hot (shared by 128 CTAs)
    const int r0 = m0 + lr, r1 = r0 + 8;

    // ==== scores accumulator = bias table (issued FIRST; latency hidden) ====
    float sc[7][4];
    {
        const int type = ((nh == 7) ? 1 : 0) | ((nw == 7) ? 2 : 0);
        int rq0 = r0 < 49 ? r0 : 48, rq1 = r1 < 49 ? r1 : 48;
        const float* bt0 = g_btab + type * TSTR + rq0 * BTP + 2 * lc;
        const float* bt1 = g_btab + type * TSTR + rq1 * BTP + 2 * lc;
#pragma unroll
        for (int nt = 0; nt < 7; ++nt) {
            *(float2*)&sc[nt][0] = __ldg((const float2*)(bt0 + nt * 8));
            *(float2*)&sc[nt][2] = __ldg((const float2*)(bt1 + nt * 8));
        }
    }
    // epilogue scatter rows (issued early, L2-hot)
    const int sr0 = __ldg(srow + (r0 < WS2 ? r0 : 0));
    const int sr1 = __ldg(srow + (r1 < WS2 ? r1 : 0));

    {   // copy weights: 1 LDG.128 + 1 STS.128 each
        int r = tid >> 2, ch = (tid & 3) << 3;
        *(uint4*)&Ms[r * MTP + ch] = *(const uint4*)&g_MT[r * 32 + ch];
        *(uint4*)&Ps[r * MTP + ch] = *(const uint4*)&g_PT[r * 32 + ch];
    }

    const size_t base = (size_t)batch * (HH * WW) * CH + head * 32;

    // ---- gather: both tiles row-major half (rows >= 49 zeroed); srow via table
    for (int idx = tid; idx < 512; idx += 128) {
        int t = idx >> 3, c4 = (idx & 7) << 2;
        float4 xv = make_float4(0.f, 0.f, 0.f, 0.f);
        float4 sv = xv;
        if (t < WS2) {
            size_t g = base + (size_t)__ldg(srow + t) * CH + c4;
            xv = *(const float4*)(x + g);
            sv = *(const float4*)(skip + g);
        }
        *(uint2*)&xr[t * XRP + c4] = make_uint2(pack_h2(xv.x, xv.y), pack_h2(xv.z, xv.w));
        *(uint2*)&ss[t * SSP + c4] = make_uint2(pack_h2(sv.x, sv.y), pack_h2(sv.z, sv.w));
    }
    __syncthreads();   // the only block-wide barrier

    // ---- LDSM lane-address bases
    const int l7 = lane & 7, lh = lane >> 3;
    const unsigned xrB = (unsigned)__cvta_generic_to_shared(xr) + 2u * (l7 * XRP + lh * 8);
    const unsigned msB = (unsigned)__cvta_generic_to_shared(Ms) + 2u * (l7 * MTP + lh * 8);
    const unsigned psB = (unsigned)__cvta_generic_to_shared(Ps) + 2u * (l7 * MTP + lh * 8);
    const unsigned xrA = (unsigned)__cvta_generic_to_shared(xr)
                       + 2u * ((m0 + ((lh & 1) << 3) + l7) * XRP + ((lh >> 1) << 3));
    const unsigned ssT = (unsigned)__cvta_generic_to_shared(ss) + 2u * ((lh * 8 + l7) * SSP);

    // ======== qm = x @ M (log2e pre-folded into M) ========
    unsigned qa[2][4];
    {
        unsigned xa[2][4];
        ldsm_x4(xrA,           xa[0][0], xa[0][1], xa[0][2], xa[0][3]);
        ldsm_x4(xrA + 2u * 16, xa[1][0], xa[1][1], xa[1][2], xa[1][3]);
#pragma unroll
        for (int np = 0; np < 2; ++np) {
            float qc[2][4];
#pragma unroll
            for (int k = 0; k < 2; ++k) {
                int nt = np * 2 + k;
                unsigned b0, b1, b2, b3;
                ldsm_x4(msB + 2u * (nt * 8 * MTP), b0, b1, b2, b3);
                float c0 = 0.f, c1 = 0.f, c2 = 0.f, c3 = 0.f;
                mma_f16(c0, c1, c2, c3, xa[0][0], xa[0][1], xa[0][2], xa[0][3], b0, b1);
                mma_f16(c0, c1, c2, c3, xa[1][0], xa[1][1], xa[1][2], xa[1][3], b2, b3);
                qc[k][0] = c0; qc[k][1] = c1; qc[k][2] = c2; qc[k][3] = c3;
            }
            qa[np][0] = pack_h2(qc[0][0], qc[0][1]);
            qa[np][1] = pack_h2(qc[0][2], qc[0][3]);
            qa[np][2] = pack_h2(qc[1][0], qc[1][1]);
            qa[np][3] = pack_h2(qc[1][2], qc[1][3]);
        }
    }

    // ======== scores = bias + qm @ x^T (bias already in accumulators) ========
#pragma unroll
    for (int nt = 0; nt < 7; ++nt) {
        unsigned b0, b1, b2, b3;
        ldsm_x4(xrB + 2u * (nt * 8 * XRP), b0, b1, b2, b3);
        mma_f16(sc[nt][0], sc[nt][1], sc[nt][2], sc[nt][3],
                qa[0][0], qa[0][1], qa[0][2], qa[0][3], b0, b1);
        mma_f16(sc[nt][0], sc[nt][1], sc[nt][2], sc[nt][3],
                qa[1][0], qa[1][1], qa[1][2], qa[1][3], b2, b3);
    }

    // ======== softmax: direct exp2, deferred normalization, NO max pass;
    //          pack probs into aa IN-PLACE so sc dies here ====
    unsigned aa[4][4];
    float inv0, inv1;
    {
        float sm0 = 0.f, sm1 = 0.f;
#pragma unroll
        for (int nt = 0; nt < 7; ++nt) {
            float p0 = ex2f(sc[nt][0]);
            float p1 = ex2f(sc[nt][1]);
            float p2 = ex2f(sc[nt][2]);
            float p3 = ex2f(sc[nt][3]);
            sm0 += p0 + p1; sm1 += p2 + p3;
            if ((nt & 1) == 0) {
                aa[nt >> 1][0] = pack_h2(p0, p1);
                aa[nt >> 1][1] = pack_h2(p2, p3);
            } else {
                aa[nt >> 1][2] = pack_h2(p0, p1);
                aa[nt >> 1][3] = pack_h2(p2, p3);
            }
        }
        aa[3][2] = 0u;
        aa[3][3] = 0u;
        sm0 += __shfl_xor_sync(0xffffffffu, sm0, 1);
        sm0 += __shfl_xor_sync(0xffffffffu, sm0, 2);
        sm1 += __shfl_xor_sync(0xffffffffu, sm1, 1);
        sm1 += __shfl_xor_sync(0xffffffffu, sm1, 2);
        inv0 = __fdividef(1.f, sm0);
        inv1 = __fdividef(1.f, sm1);
    }

    // ======== T = probs @ skip_v (B via ldmatrix.trans) ========
    unsigned ta[2][4];
    {
        float tc[4][4];
#pragma unroll
        for (int nt = 0; nt < 4; ++nt) {
            float c0 = 0.f, c1 = 0.f, c2 = 0.f, c3 = 0.f;
#pragma unroll
            for (int tg = 0; tg < 2; ++tg) {
                unsigned b0, b1, b2, b3;
                ldsm_x4_t(ssT + 2u * (tg * 32 * SSP + nt * 8), b0, b1, b2, b3);
                mma_f16(c0, c1, c2, c3,
                        aa[2 * tg][0], aa[2 * tg][1], aa[2 * tg][2], aa[2 * tg][3], b0, b1);
                mma_f16(c0, c1, c2, c3,
                        aa[2 * tg + 1][0], aa[2 * tg + 1][1], aa[2 * tg + 1][2], aa[2 * tg + 1][3], b2, b3);
            }
            tc[nt][0] = c0; tc[nt][1] = c1; tc[nt][2] = c2; tc[nt][3] = c3;
        }
#pragma unroll
        for (int kk = 0; kk < 2; ++kk) {
            ta[kk][0] = pack_h2(tc[2 * kk][0],     tc[2 * kk][1]);
            ta[kk][1] = pack_h2(tc[2 * kk][2],     tc[2 * kk][3]);
            ta[kk][2] = pack_h2(tc[2 * kk + 1][0], tc[2 * kk + 1][1]);
            ta[kk][3] = pack_h2(tc[2 * kk + 1][2], tc[2 * kk + 1][3]);
        }
    }

    // ======== out = T @ P, scale rows by 1/sum, write ========
    {
        bool w0 = r0 < WS2, w1 = r1 < WS2;
        size_t g0 = base + (size_t)sr0 * CH;
        size_t g1 = base + (size_t)sr1 * CH;
#pragma unroll
        for (int nt = 0; nt < 4; ++nt) {
            unsigned b0, b1, b2, b3;
            ldsm_x4(psB + 2u * (nt * 8 * MTP), b0, b1, b2, b3);
            float c0 = 0.f, c1 = 0.f, c2 = 0.f, c3 = 0.f;
            mma_f16(c0, c1, c2, c3, ta[0][0], ta[0][1], ta[0][2], ta[0][3], b0, b1);
            mma_f16(c0, c1, c2, c3, ta[1][0], ta[1][1], ta[1][2], ta[1][3], b2, b3);
            int col = nt * 8 + 2 * lc;
            if (w0) *(float2*)(out + g0 + col) = make_float2(c0 * inv0, c1 * inv0);
            if (w1) *(float2*)(out + g1 + col) = make_float2(c2 * inv1, c3 * inv1);
        }
    }
}

extern "C" void kernel_launch(void* const* d_in, const int* in_sizes, int n_in,
                              void* d_out, int out_size) {
    const float* skip = (const float*)d_in[0];
    const float* x    = (const float*)d_in[1];
    const float* Wq   = (const float*)d_in[2];
    const float* Wk   = (const float*)d_in[3];
    const float* Wv   = (const float*)d_in[4];
    const float* Wl   = (const float*)d_in[5];
    const float* pe   = (const float*)d_in[6];
    (void)in_sizes; (void)n_in; (void)out_size;

    precompute_kernel<<<64, 128>>>(Wq, Wk, Wv, Wl, pe);
    dim3 grid(64, 8, 16);
    swca_kernel<<<grid, 128>>>(x, skip, (float*)d_out);
}

// round 16
// speedup vs baseline: 1.1015x; 1.0150x over previous
#include <cuda_runtime.h>
#include <cuda_fp16.h>
#include <math.h>

#define DISP 3
#define CH   256
#define HH   56
#define WW   56
#define WS2  49
#define XRP  40    // xr pitch (halves) — 80B row stride, LDSM conflict-free
#define SSP  40    // ss pitch (halves), row-major
#define MTP  40    // MT/PT pitch (halves)
#define BTP  56    // btab row pitch (floats): cols 49..55 = -1e30 padding
#define TSTR 2752  // per-type btab stride (floats)

__device__ __half g_MT[1024];  // MT[n][k] = (Wq^T Wk / sqrt32 * log2e)[k][n]
__device__ __half g_PT[1024];  // PT[n][k] = (Wv^T Wl^T)[k][n]
__device__ __align__(16) float g_btab[4 * TSTR];  // bias-2 (log2e) or -1e30; L1/L2-hot

__device__ __forceinline__ unsigned pack_h2(float lo, float hi) {
    unsigned u;
    asm("cvt.rn.f16x2.f32 %0, %1, %2;" : "=r"(u) : "f"(hi), "f"(lo));
    return u;
}
__device__ __forceinline__ float ex2f(float x) {
    float r; asm("ex2.approx.f32 %0, %1;" : "=f"(r) : "f"(x));
    return r;
}

__device__ __forceinline__ void mma_f16(float& c0, float& c1, float& c2, float& c3,
                                        unsigned a0, unsigned a1, unsigned a2, unsigned a3,
                                        unsigned b0, unsigned b1) {
    asm volatile("mma.sync.aligned.m16n8k16.row.col.f32.f16.f16.f32 "
        "{%0,%1,%2,%3}, {%4,%5,%6,%7}, {%8,%9}, {%0,%1,%2,%3};"
        : "+f"(c0), "+f"(c1), "+f"(c2), "+f"(c3)
        : "r"(a0), "r"(a1), "r"(a2), "r"(a3), "r"(b0), "r"(b1));
}

__device__ __forceinline__ void ldsm_x4(unsigned addr, unsigned& r0, unsigned& r1,
                                        unsigned& r2, unsigned& r3) {
    asm volatile("ldmatrix.sync.aligned.m8n8.x4.shared.b16 {%0,%1,%2,%3}, [%4];"
        : "=r"(r0), "=r"(r1), "=r"(r2), "=r"(r3) : "r"(addr));
}
__device__ __forceinline__ void ldsm_x4_t(unsigned addr, unsigned& r0, unsigned& r1,
                                          unsigned& r2, unsigned& r3) {
    asm volatile("ldmatrix.sync.aligned.m8n8.x4.trans.shared.b16 {%0,%1,%2,%3}, [%4];"
        : "=r"(r0), "=r"(r1), "=r"(r2), "=r"(r3) : "r"(addr));
}

#define LOG2E 1.4426950408889634f

__global__ void precompute_kernel(const float* __restrict__ Wq,
                                  const float* __restrict__ Wk,
                                  const float* __restrict__ Wv,
                                  const float* __restrict__ Wl,
                                  const float* __restrict__ pe) {
    int i = blockIdx.x * 128 + threadIdx.x;   // 0..8191
    if (i < 1024) {   // fused weights
        int c = i >> 5, d = i & 31;
        float m = 0.f, p = 0.f;
#pragma unroll
        for (int j = 0; j < 32; ++j) {
            m += Wq[j * 32 + c] * Wk[j * 32 + d];   // (Wq^T Wk)[c][d]
            p += Wv[j * 32 + c] * Wl[d * 32 + j];   // (Wv^T Wl^T)[c][d]
        }
        g_MT[d * 32 + c] = __float2half_rn(m * 0.17677669529663687f * LOG2E);
        g_PT[d * 32 + c] = __float2half_rn(p);
    }
    // bias+mask tables: 4 types x 49 rows x BTP cols; masked/pad = -1e30
    for (int e = i; e < 4 * TSTR; e += 8192) {
        int type = e / TSTR, rem = e - type * TSTR;
        float v = -1e30f;
        if (rem < 49 * BTP) {
            int r = rem / BTP, cl = rem - r * BTP;
            if (cl < 49) {
                int qi = r / 7, qj = r - qi * 7;
                int ki = cl / 7, kj = cl - ki * 7;
                bool mrow = type & 1, mcol = type & 2;
                bool dead = (mrow && ((qi >= 4) != (ki >= 4))) ||
                            (mcol && ((qj >= 4) != (kj >= 4)));
                v = dead ? -1e30f : pe[(ki - qi + 6) * 13 + (kj - qj + 6)] * LOG2E - 2.0f;
            }
        }
        g_btab[e] = v;
    }
}

__global__ __launch_bounds__(128, 8)
void swca_kernel(const float* __restrict__ x, const float* __restrict__ skip,
                 float* __restrict__ out) {
    const int win   = blockIdx.x;   // 0..63
    const int head  = blockIdx.y;
    const int batch = blockIdx.z;
    const int nh = win >> 3, nw = win & 7;
    const int tid  = threadIdx.x;
    const int lane = tid & 31, warp = tid >> 5;
    const int lr = lane >> 2, lc = lane & 3;
    const int m0 = warp * 16;

    __shared__ __align__(16) __half xr[64 * XRP];   // x tile row-major [token][d]
    __shared__ __align__(16) __half ss[64 * SSP];   // skip tile row-major [token][d]
    __shared__ __align__(16) __half Ms[32 * MTP];
    __shared__ __align__(16) __half Ps[32 * MTP];
    __shared__ int srow[WS2];

    const int r0 = m0 + lr, r1 = r0 + 8;

    // ==== scores accumulator = bias table (issued FIRST; latency hidden) ====
    float sc[7][4];
    {
        const int type = ((nh == 7) ? 1 : 0) | ((nw == 7) ? 2 : 0);
        int rq0 = r0 < 49 ? r0 : 48, rq1 = r1 < 49 ? r1 : 48;
        const float* bt0 = g_btab + type * TSTR + rq0 * BTP + 2 * lc;
        const float* bt1 = g_btab + type * TSTR + rq1 * BTP + 2 * lc;
#pragma unroll
        for (int nt = 0; nt < 7; ++nt) {
            *(float2*)&sc[nt][0] = __ldg((const float2*)(bt0 + nt * 8));
            *(float2*)&sc[nt][2] = __ldg((const float2*)(bt1 + nt * 8));
        }
    }

    {   // copy weights: 1 LDG.128 + 1 STS.128 each
        int r = tid >> 2, ch = (tid & 3) << 3;
        *(uint4*)&Ms[r * MTP + ch] = *(const uint4*)&g_MT[r * 32 + ch];
        *(uint4*)&Ps[r * MTP + ch] = *(const uint4*)&g_PT[r * 32 + ch];
    }

    const size_t base = (size_t)batch * (HH * WW) * CH + head * 32;

    // ---- gather: both tiles row-major half (rows >= 49 zeroed), inline index math
    for (int idx = tid; idx < 512; idx += 128) {
        int t = idx >> 3, c4 = (idx & 7) << 2;
        float4 xv = make_float4(0.f, 0.f, 0.f, 0.f);
        float4 sv = xv;
        if (t < WS2) {
            int wi = t / 7, wj = t - wi * 7;
            int r  = nh * 7 + wi + DISP;  if (r  >= HH) r  -= HH;
            int cc = nw * 7 + wj + DISP;  if (cc >= WW) cc -= WW;
            int sr = r * WW + cc;
            if (c4 == 0) srow[t] = sr;
            size_t g = base + (size_t)sr * CH + c4;
            xv = *(const float4*)(x + g);
            sv = *(const float4*)(skip + g);
        }
        *(uint2*)&xr[t * XRP + c4] = make_uint2(pack_h2(xv.x, xv.y), pack_h2(xv.z, xv.w));
        *(uint2*)&ss[t * SSP + c4] = make_uint2(pack_h2(sv.x, sv.y), pack_h2(sv.z, sv.w));
    }
    __syncthreads();   // the only block-wide barrier

    // ---- LDSM lane-address bases
    const int l7 = lane & 7, lh = lane >> 3;
    const unsigned xrB = (unsigned)__cvta_generic_to_shared(xr) + 2u * (l7 * XRP + lh * 8);
    const unsigned msB = (unsigned)__cvta_generic_to_shared(Ms) + 2u * (l7 * MTP + lh * 8);
    const unsigned psB = (unsigned)__cvta_generic_to_shared(Ps) + 2u * (l7 * MTP + lh * 8);
    const unsigned xrA = (unsigned)__cvta_generic_to_shared(xr)
                       + 2u * ((m0 + ((lh & 1) << 3) + l7) * XRP + ((lh >> 1) << 3));
    const unsigned ssT = (unsigned)__cvta_generic_to_shared(ss) + 2u * ((lh * 8 + l7) * SSP);

    // ======== qm = x @ M (software-pipelined B loads) ========
    unsigned qa[2][4];
    {
        unsigned xa[2][4];
        ldsm_x4(xrA,           xa[0][0], xa[0][1], xa[0][2], xa[0][3]);
        ldsm_x4(xrA + 2u * 16, xa[1][0], xa[1][1], xa[1][2], xa[1][3]);
        unsigned mb[2][4];
        ldsm_x4(msB, mb[0][0], mb[0][1], mb[0][2], mb[0][3]);
        float qc[4][4];
#pragma unroll
        for (int nt = 0; nt < 4; ++nt) {
            if (nt < 3)
                ldsm_x4(msB + 2u * ((nt + 1) * 8 * MTP),
                        mb[(nt + 1) & 1][0], mb[(nt + 1) & 1][1],
                        mb[(nt + 1) & 1][2], mb[(nt + 1) & 1][3]);
            float c0 = 0.f, c1 = 0.f, c2 = 0.f, c3 = 0.f;
            mma_f16(c0, c1, c2, c3, xa[0][0], xa[0][1], xa[0][2], xa[0][3],
                    mb[nt & 1][0], mb[nt & 1][1]);
            mma_f16(c0, c1, c2, c3, xa[1][0], xa[1][1], xa[1][2], xa[1][3],
                    mb[nt & 1][2], mb[nt & 1][3]);
            qc[nt][0] = c0; qc[nt][1] = c1; qc[nt][2] = c2; qc[nt][3] = c3;
        }
#pragma unroll
        for (int kk = 0; kk < 2; ++kk) {
            qa[kk][0] = pack_h2(qc[2 * kk][0],     qc[2 * kk][1]);
            qa[kk][1] = pack_h2(qc[2 * kk][2],     qc[2 * kk][3]);
            qa[kk][2] = pack_h2(qc[2 * kk + 1][0], qc[2 * kk + 1][1]);
            qa[kk][3] = pack_h2(qc[2 * kk + 1][2], qc[2 * kk + 1][3]);
        }
    }

    // ======== scores = bias + qm @ x^T (pipelined B loads) ========
    {
        unsigned kb[2][4];
        ldsm_x4(xrB, kb[0][0], kb[0][1], kb[0][2], kb[0][3]);
#pragma unroll
        for (int nt = 0; nt < 7; ++nt) {
            if (nt < 6)
                ldsm_x4(xrB + 2u * ((nt + 1) * 8 * XRP),
                        kb[(nt + 1) & 1][0], kb[(nt + 1) & 1][1],
                        kb[(nt + 1) & 1][2], kb[(nt + 1) & 1][3]);
            mma_f16(sc[nt][0], sc[nt][1], sc[nt][2], sc[nt][3],
                    qa[0][0], qa[0][1], qa[0][2], qa[0][3],
                    kb[nt & 1][0], kb[nt & 1][1]);
            mma_f16(sc[nt][0], sc[nt][1], sc[nt][2], sc[nt][3],
                    qa[1][0], qa[1][1], qa[1][2], qa[1][3],
                    kb[nt & 1][2], kb[nt & 1][3]);
        }
    }

    // ======== softmax: direct exp2, deferred normalization, in-place pack ========
    unsigned aa[4][4];
    float inv0, inv1;
    {
        float sm0 = 0.f, sm1 = 0.f;
#pragma unroll
        for (int nt = 0; nt < 7; ++nt) {
            float p0 = ex2f(sc[nt][0]);
            float p1 = ex2f(sc[nt][1]);
            float p2 = ex2f(sc[nt][2]);
            float p3 = ex2f(sc[nt][3]);
            sm0 += p0 + p1; sm1 += p2 + p3;
            if ((nt & 1) == 0) {
                aa[nt >> 1][0] = pack_h2(p0, p1);
                aa[nt >> 1][1] = pack_h2(p2, p3);
            } else {
                aa[nt >> 1][2] = pack_h2(p0, p1);
                aa[nt >> 1][3] = pack_h2(p2, p3);
            }
        }
        aa[3][2] = 0u;
        aa[3][3] = 0u;
        sm0 += __shfl_xor_sync(0xffffffffu, sm0, 1);
        sm0 += __shfl_xor_sync(0xffffffffu, sm0, 2);
        sm1 += __shfl_xor_sync(0xffffffffu, sm1, 1);
        sm1 += __shfl_xor_sync(0xffffffffu, sm1, 2);
        inv0 = __fdividef(1.f, sm0);
        inv1 = __fdividef(1.f, sm1);
    }

    // ======== T = probs @ skip_v (pipelined trans B loads); scale rows in pack ====
    unsigned ta[2][4];
    {
        float tc[4][4];
#pragma unroll
        for (int nt = 0; nt < 4; ++nt)
#pragma unroll
            for (int j = 0; j < 4; ++j) tc[nt][j] = 0.f;

        unsigned vb[2][4];
        ldsm_x4_t(ssT, vb[0][0], vb[0][1], vb[0][2], vb[0][3]);
#pragma unroll
        for (int i = 0; i < 8; ++i) {      // i = nt*2 + tg
            int nt = i >> 1, tg = i & 1;
            if (i < 7) {
                int ntn = (i + 1) >> 1, tgn = (i + 1) & 1;
                ldsm_x4_t(ssT + 2u * (tgn * 32 * SSP + ntn * 8),
                          vb[(i + 1) & 1][0], vb[(i + 1) & 1][1],
                          vb[(i + 1) & 1][2], vb[(i + 1) & 1][3]);
            }
            mma_f16(tc[nt][0], tc[nt][1], tc[nt][2], tc[nt][3],
                    aa[2 * tg][0], aa[2 * tg][1], aa[2 * tg][2], aa[2 * tg][3],
                    vb[i & 1][0], vb[i & 1][1]);
            mma_f16(tc[nt][0], tc[nt][1], tc[nt][2], tc[nt][3],
                    aa[2 * tg + 1][0], aa[2 * tg + 1][1], aa[2 * tg + 1][2], aa[2 * tg + 1][3],
                    vb[i & 1][2], vb[i & 1][3]);
        }
#pragma unroll
        for (int kk = 0; kk < 2; ++kk) {
            ta[kk][0] = pack_h2(tc[2 * kk][0] * inv0,     tc[2 * kk][1] * inv0);
            ta[kk][1] = pack_h2(tc[2 * kk][2] * inv1,     tc[2 * kk][3] * inv1);
            ta[kk][2] = pack_h2(tc[2 * kk + 1][0] * inv0, tc[2 * kk + 1][1] * inv0);
            ta[kk][3] = pack_h2(tc[2 * kk + 1][2] * inv1, tc[2 * kk + 1][3] * inv1);
        }
    }

    // ======== out = T @ P (pipelined B loads), direct store ========
    {
        bool w0 = r0 < WS2, w1 = r1 < WS2;
        size_t g0 = base + (size_t)srow[w0 ? r0 : 0] * CH;
        size_t g1 = base + (size_t)srow[w1 ? r1 : 0] * CH;
        unsigned pb[2][4];
        ldsm_x4(psB, pb[0][0], pb[0][1], pb[0][2], pb[0][3]);
#pragma unroll
        for (int nt = 0; nt < 4; ++nt) {
            if (nt < 3)
                ldsm_x4(psB + 2u * ((nt + 1) * 8 * MTP),
                        pb[(nt + 1) & 1][0], pb[(nt + 1) & 1][1],
                        pb[(nt + 1) & 1][2], pb[(nt + 1) & 1][3]);
            float c0 = 0.f, c1 = 0.f, c2 = 0.f, c3 = 0.f;
            mma_f16(c0, c1, c2, c3, ta[0][0], ta[0][1], ta[0][2], ta[0][3],
                    pb[nt & 1][0], pb[nt & 1][1]);
            mma_f16(c0, c1, c2, c3, ta[1][0], ta[1][1], ta[1][2], ta[1][3],
                    pb[nt & 1][2], pb[nt & 1][3]);
            int col = nt * 8 + 2 * lc;
            if (w0) *(float2*)(out + g0 + col) = make_float2(c0, c1);
            if (w1) *(float2*)(out + g1 + col) = make_float2(c2, c3);
        }
    }
}

extern "C" void kernel_launch(void* const* d_in, const int* in_sizes, int n_in,
                              void* d_out, int out_size) {
    const float* skip = (const float*)d_in[0];
    const float* x    = (const float*)d_in[1];
    const float* Wq   = (const float*)d_in[2];
    const float* Wk   = (const float*)d_in[3];
    const float* Wv   = (const float*)d_in[4];
    const float* Wl   = (const float*)d_in[5];
    const float* pe   = (const float*)d_in[6];
    (void)in_sizes; (void)n_in; (void)out_size;

    precompute_kernel<<<64, 128>>>(Wq, Wk, Wv, Wl, pe);
    dim3 grid(64, 8, 16);
    swca_kernel<<<grid, 128>>>(x, skip, (float*)d_out);
}

// round 17
// speedup vs baseline: 1.1801x; 1.0713x over previous
#include <cuda_runtime.h>
#include <cuda_fp16.h>
#include <math.h>

#define DISP 3
#define CH   256
#define HH   56
#define WW   56
#define WS2  49
#define XRP  40    // xr pitch (halves) — 80B row stride, LDSM conflict-free
#define SSP  40    // ss pitch (halves), row-major
#define MTP  40    // MT/PT pitch (halves)
#define BTP  56    // btab row pitch (floats): cols 49..55 = -1e30 padding
#define TSTR 2752  // per-type btab stride (floats), 49*56=2744 padded

__device__ __half g_MT[1024];  // MT[n][k] = (Wq^T Wk / sqrt32 * log2e)[k][n]
__device__ __half g_PT[1024];  // PT[n][k] = (Wv^T Wl^T)[k][n]
__device__ __align__(16) float g_btab[4 * TSTR];  // bias-2 (log2e) or -1e30; L1/L2-hot

__device__ __forceinline__ unsigned pack_h2(float lo, float hi) {
    unsigned u;
    asm("cvt.rn.f16x2.f32 %0, %1, %2;" : "=r"(u) : "f"(hi), "f"(lo));
    return u;
}
__device__ __forceinline__ float ex2f(float x) {
    float r; asm("ex2.approx.f32 %0, %1;" : "=f"(r) : "f"(x));
    return r;
}

__device__ __forceinline__ void mma_f16(float& c0, float& c1, float& c2, float& c3,
                                        unsigned a0, unsigned a1, unsigned a2, unsigned a3,
                                        unsigned b0, unsigned b1) {
    asm volatile("mma.sync.aligned.m16n8k16.row.col.f32.f16.f16.f32 "
        "{%0,%1,%2,%3}, {%4,%5,%6,%7}, {%8,%9}, {%0,%1,%2,%3};"
        : "+f"(c0), "+f"(c1), "+f"(c2), "+f"(c3)
        : "r"(a0), "r"(a1), "r"(a2), "r"(a3), "r"(b0), "r"(b1));
}

__device__ __forceinline__ void ldsm_x4(unsigned addr, unsigned& r0, unsigned& r1,
                                        unsigned& r2, unsigned& r3) {
    asm volatile("ldmatrix.sync.aligned.m8n8.x4.shared.b16 {%0,%1,%2,%3}, [%4];"
        : "=r"(r0), "=r"(r1), "=r"(r2), "=r"(r3) : "r"(addr));
}
__device__ __forceinline__ void ldsm_x4_t(unsigned addr, unsigned& r0, unsigned& r1,
                                          unsigned& r2, unsigned& r3) {
    asm volatile("ldmatrix.sync.aligned.m8n8.x4.trans.shared.b16 {%0,%1,%2,%3}, [%4];"
        : "=r"(r0), "=r"(r1), "=r"(r2), "=r"(r3) : "r"(addr));
}

#define LOG2E 1.4426950408889634f

__global__ void precompute_kernel(const float* __restrict__ Wq,
                                  const float* __restrict__ Wk,
                                  const float* __restrict__ Wv,
                                  const float* __restrict__ Wl,
                                  const float* __restrict__ pe) {
    int i = blockIdx.x * 128 + threadIdx.x;   // 0..8191
    if (i < 1024) {   // fused weights
        int c = i >> 5, d = i & 31;
        float m = 0.f, p = 0.f;
#pragma unroll
        for (int j = 0; j < 32; ++j) {
            m += Wq[j * 32 + c] * Wk[j * 32 + d];   // (Wq^T Wk)[c][d]
            p += Wv[j * 32 + c] * Wl[d * 32 + j];   // (Wv^T Wl^T)[c][d]
        }
        g_MT[d * 32 + c] = __float2half_rn(m * 0.17677669529663687f * LOG2E);
        g_PT[d * 32 + c] = __float2half_rn(p);
    }
    // bias+mask tables: 4 types x 49 rows x BTP cols; masked/pad = -1e30
    for (int e = i; e < 4 * TSTR; e += 8192) {
        int type = e / TSTR, rem = e - type * TSTR;
        float v = -1e30f;
        if (rem < 49 * BTP) {
            int r = rem / BTP, cl = rem - r * BTP;
            if (cl < 49) {
                int qi = r / 7, qj = r - qi * 7;
                int ki = cl / 7, kj = cl - ki * 7;
                bool mrow = type & 1, mcol = type & 2;
                bool dead = (mrow && ((qi >= 4) != (ki >= 4))) ||
                            (mcol && ((qj >= 4) != (kj >= 4)));
                v = dead ? -1e30f : pe[(ki - qi + 6) * 13 + (kj - qj + 6)] * LOG2E - 2.0f;
            }
        }
        g_btab[e] = v;
    }
}

__global__ __launch_bounds__(128, 8)
void swca_kernel(const float* __restrict__ x, const float* __restrict__ skip,
                 float* __restrict__ out) {
    const int win   = blockIdx.x;   // 0..63
    const int head  = blockIdx.y;
    const int batch = blockIdx.z;
    const int nh = win >> 3, nw = win & 7;
    const int tid  = threadIdx.x;
    const int lane = tid & 31, warp = tid >> 5;
    const int lr = lane >> 2, lc = lane & 3;
    const int m0 = warp * 16;

    __shared__ __align__(16) __half xr[64 * XRP];   // x tile row-major [token][d]
    __shared__ __align__(16) __half ss[64 * SSP];   // skip tile row-major [token][d]
    __shared__ __align__(16) __half Ms[32 * MTP];
    __shared__ __align__(16) __half Ps[32 * MTP];
    __shared__ int srow[WS2];

    // ==== scores accumulator = bias table (issued FIRST; latency hidden by
    //      gather + qm GEMM; L1-resident after first CTAs on each SM) ====
    const int r0 = m0 + lr, r1 = r0 + 8;
    float sc[7][4];
    {
        const int type = ((nh == 7) ? 1 : 0) | ((nw == 7) ? 2 : 0);
        int rq0 = r0 < 49 ? r0 : 48, rq1 = r1 < 49 ? r1 : 48;
        const float* bt0 = g_btab + type * TSTR + rq0 * BTP + 2 * lc;
        const float* bt1 = g_btab + type * TSTR + rq1 * BTP + 2 * lc;
#pragma unroll
        for (int nt = 0; nt < 7; ++nt) {
            *(float2*)&sc[nt][0] = __ldg((const float2*)(bt0 + nt * 8));
            *(float2*)&sc[nt][2] = __ldg((const float2*)(bt1 + nt * 8));
        }
    }

    {   // copy weights: 1 LDG.128 + 1 STS.128 each
        int r = tid >> 2, ch = (tid & 3) << 3;
        *(uint4*)&Ms[r * MTP + ch] = *(const uint4*)&g_MT[r * 32 + ch];
        *(uint4*)&Ps[r * MTP + ch] = *(const uint4*)&g_PT[r * 32 + ch];
    }

    const size_t base = (size_t)batch * (HH * WW) * CH + head * 32;

    // ---- gather: both tiles row-major half (rows >= 49 zeroed), inline index math
    for (int idx = tid; idx < 512; idx += 128) {
        int t = idx >> 3, c4 = (idx & 7) << 2;
        float4 xv = make_float4(0.f, 0.f, 0.f, 0.f);
        float4 sv = xv;
        if (t < WS2) {
            int wi = t / 7, wj = t - wi * 7;
            int r  = nh * 7 + wi + DISP;  if (r  >= HH) r  -= HH;
            int cc = nw * 7 + wj + DISP;  if (cc >= WW) cc -= WW;
            int sr = r * WW + cc;
            if (c4 == 0) srow[t] = sr;
            size_t g = base + (size_t)sr * CH + c4;
            xv = *(const float4*)(x + g);
            sv = *(const float4*)(skip + g);
        }
        *(uint2*)&xr[t * XRP + c4] = make_uint2(pack_h2(xv.x, xv.y), pack_h2(xv.z, xv.w));
        *(uint2*)&ss[t * SSP + c4] = make_uint2(pack_h2(sv.x, sv.y), pack_h2(sv.z, sv.w));
    }
    __syncthreads();   // the only block-wide barrier

    // ---- LDSM lane-address bases
    const int l7 = lane & 7, lh = lane >> 3;
    const unsigned xrB = (unsigned)__cvta_generic_to_shared(xr) + 2u * (l7 * XRP + lh * 8);
    const unsigned msB = (unsigned)__cvta_generic_to_shared(Ms) + 2u * (l7 * MTP + lh * 8);
    const unsigned psB = (unsigned)__cvta_generic_to_shared(Ps) + 2u * (l7 * MTP + lh * 8);
    const unsigned xrA = (unsigned)__cvta_generic_to_shared(xr)
                       + 2u * ((m0 + ((lh & 1) << 3) + l7) * XRP + ((lh >> 1) << 3));
    const unsigned ssT = (unsigned)__cvta_generic_to_shared(ss) + 2u * ((lh * 8 + l7) * SSP);

    // ======== qm = x @ M (log2e pre-folded into M) ========
    unsigned qa[2][4];
    {
        unsigned xa[2][4];
        ldsm_x4(xrA,           xa[0][0], xa[0][1], xa[0][2], xa[0][3]);
        ldsm_x4(xrA + 2u * 16, xa[1][0], xa[1][1], xa[1][2], xa[1][3]);
#pragma unroll
        for (int np = 0; np < 2; ++np) {   // pack per pair of n-tiles to limit qc liveness
            float qc[2][4];
#pragma unroll
            for (int k = 0; k < 2; ++k) {
                int nt = np * 2 + k;
                unsigned b0, b1, b2, b3;
                ldsm_x4(msB + 2u * (nt * 8 * MTP), b0, b1, b2, b3);
                float c0 = 0.f, c1 = 0.f, c2 = 0.f, c3 = 0.f;
                mma_f16(c0, c1, c2, c3, xa[0][0], xa[0][1], xa[0][2], xa[0][3], b0, b1);
                mma_f16(c0, c1, c2, c3, xa[1][0], xa[1][1], xa[1][2], xa[1][3], b2, b3);
                qc[k][0] = c0; qc[k][1] = c1; qc[k][2] = c2; qc[k][3] = c3;
            }
            qa[np][0] = pack_h2(qc[0][0], qc[0][1]);
            qa[np][1] = pack_h2(qc[0][2], qc[0][3]);
            qa[np][2] = pack_h2(qc[1][0], qc[1][1]);
            qa[np][3] = pack_h2(qc[1][2], qc[1][3]);
        }
    }

    // ======== scores = bias + qm @ x^T (bias already in accumulators) ========
#pragma unroll
    for (int nt = 0; nt < 7; ++nt) {
        unsigned b0, b1, b2, b3;
        ldsm_x4(xrB + 2u * (nt * 8 * XRP), b0, b1, b2, b3);
        mma_f16(sc[nt][0], sc[nt][1], sc[nt][2], sc[nt][3],
                qa[0][0], qa[0][1], qa[0][2], qa[0][3], b0, b1);
        mma_f16(sc[nt][0], sc[nt][1], sc[nt][2], sc[nt][3],
                qa[1][0], qa[1][1], qa[1][2], qa[1][3], b2, b3);
    }

    // ======== softmax: direct exp2, deferred normalization, NO max pass ========
    float inv0, inv1;
    {
        float sm0 = 0.f, sm1 = 0.f;
#pragma unroll
        for (int nt = 0; nt < 7; ++nt) {
            float p0 = ex2f(sc[nt][0]);
            float p1 = ex2f(sc[nt][1]);
            float p2 = ex2f(sc[nt][2]);
            float p3 = ex2f(sc[nt][3]);
            sc[nt][0] = p0; sc[nt][1] = p1; sc[nt][2] = p2; sc[nt][3] = p3;
            sm0 += p0 + p1; sm1 += p2 + p3;
        }
        sm0 += __shfl_xor_sync(0xffffffffu, sm0, 1);
        sm0 += __shfl_xor_sync(0xffffffffu, sm0, 2);
        sm1 += __shfl_xor_sync(0xffffffffu, sm1, 1);
        sm1 += __shfl_xor_sync(0xffffffffu, sm1, 2);
        inv0 = __fdividef(1.f, sm0);
        inv1 = __fdividef(1.f, sm1);
    }

    // ======== probs C-frags -> A-frags via f16x2 packs ========
    unsigned aa[4][4];
#pragma unroll
    for (int kk = 0; kk < 3; ++kk) {
        aa[kk][0] = pack_h2(sc[2 * kk][0],     sc[2 * kk][1]);
        aa[kk][1] = pack_h2(sc[2 * kk][2],     sc[2 * kk][3]);
        aa[kk][2] = pack_h2(sc[2 * kk + 1][0], sc[2 * kk + 1][1]);
        aa[kk][3] = pack_h2(sc[2 * kk + 1][2], sc[2 * kk + 1][3]);
    }
    aa[3][0] = pack_h2(sc[6][0], sc[6][1]);
    aa[3][1] = pack_h2(sc[6][2], sc[6][3]);
    aa[3][2] = 0u;
    aa[3][3] = 0u;

    // ======== T = probs @ skip_v (B via ldmatrix.trans) ========
    unsigned ta[2][4];
    {
        float tc[4][4];
#pragma unroll
        for (int nt = 0; nt < 4; ++nt) {
            float c0 = 0.f, c1 = 0.f, c2 = 0.f, c3 = 0.f;
#pragma unroll
            for (int tg = 0; tg < 2; ++tg) {
                unsigned b0, b1, b2, b3;
                ldsm_x4_t(ssT + 2u * (tg * 32 * SSP + nt * 8), b0, b1, b2, b3);
                mma_f16(c0, c1, c2, c3,
                        aa[2 * tg][0], aa[2 * tg][1], aa[2 * tg][2], aa[2 * tg][3], b0, b1);
                mma_f16(c0, c1, c2, c3,
                        aa[2 * tg + 1][0], aa[2 * tg + 1][1], aa[2 * tg + 1][2], aa[2 * tg + 1][3], b2, b3);
            }
            tc[nt][0] = c0; tc[nt][1] = c1; tc[nt][2] = c2; tc[nt][3] = c3;
        }
#pragma unroll
        for (int kk = 0; kk < 2; ++kk) {
            ta[kk][0] = pack_h2(tc[2 * kk][0],     tc[2 * kk][1]);
            ta[kk][1] = pack_h2(tc[2 * kk][2],     tc[2 * kk][3]);
            ta[kk][2] = pack_h2(tc[2 * kk + 1][0], tc[2 * kk + 1][1]);
            ta[kk][3] = pack_h2(tc[2 * kk + 1][2], tc[2 * kk + 1][3]);
        }
    }

    // ======== out = T @ P, scale rows by 1/sum, write ========
    {
        bool w0 = r0 < WS2, w1 = r1 < WS2;
        size_t g0 = w0 ? base + (size_t)srow[r0] * CH : 0;
        size_t g1 = w1 ? base + (size_t)srow[r1 < WS2 ? r1 : 0] * CH : 0;
#pragma unroll
        for (int nt = 0; nt < 4; ++nt) {
            unsigned b0, b1, b2, b3;
            ldsm_x4(psB + 2u * (nt * 8 * MTP), b0, b1, b2, b3);
            float c0 = 0.f, c1 = 0.f, c2 = 0.f, c3 = 0.f;
            mma_f16(c0, c1, c2, c3, ta[0][0], ta[0][1], ta[0][2], ta[0][3], b0, b1);
            mma_f16(c0, c1, c2, c3, ta[1][0], ta[1][1], ta[1][2], ta[1][3], b2, b3);
            int col = nt * 8 + 2 * lc;
            if (w0) *(float2*)(out + g0 + col) = make_float2(c0 * inv0, c1 * inv0);
            if (w1) *(float2*)(out + g1 + col) = make_float2(c2 * inv1, c3 * inv1);
        }
    }
}

extern "C" void kernel_launch(void* const* d_in, const int* in_sizes, int n_in,
                              void* d_out, int out_size) {
    const float* skip = (const float*)d_in[0];
    const float* x    = (const float*)d_in[1];
    const float* Wq   = (const float*)d_in[2];
    const float* Wk   = (const float*)d_in[3];
    const float* Wv   = (const float*)d_in[4];
    const float* Wl   = (const float*)d_in[5];
    const float* pe   = (const float*)d_in[6];
    (void)in_sizes; (void)n_in; (void)out_size;

    precompute_kernel<<<64, 128>>>(Wq, Wk, Wv, Wl, pe);
    dim3 grid(64, 8, 16);
    swca_kernel<<<grid, 128>>>(x, skip, (float*)d_out);
}